// round 2
// baseline (speedup 1.0000x reference)
#include <cuda_runtime.h>
#include <cstdint>

// Problem: x [4,512,128] f32, y [512,128] f32
// out [4,512,512,3] f32 : (cosine, L1, L2) per pair.
// R = 4*512 = 2048 flattened x rows, C = 512 y rows, D = 128.

#define R_TOTAL 2048
#define C_TOTAL 512
#define D_DIM   128

#define BM 128          // x rows per block
#define BN 64           // y rows per block
#define DK 32           // D chunk
#define PADW 4          // pad words (keeps 16B alignment, spreads banks)
#define LDW (DK + PADW) // 36 words per smem row

typedef unsigned long long u64;
struct __align__(16) ull2 { u64 x, y; };

// ---------------- precomputed norms ----------------
__device__ float g_xsq[R_TOTAL];
__device__ float g_xrn[R_TOTAL];
__device__ float g_ysq[C_TOTAL];
__device__ float g_yrn[C_TOTAL];

__global__ void norms_kernel(const float* __restrict__ x,
                             const float* __restrict__ y) {
    int w    = (blockIdx.x * blockDim.x + threadIdx.x) >> 5;
    int lane = threadIdx.x & 31;
    if (w >= R_TOTAL + C_TOTAL) return;
    const float* p = (w < R_TOTAL) ? (x + (size_t)w * D_DIM)
                                   : (y + (size_t)(w - R_TOTAL) * D_DIM);
    float4 v = reinterpret_cast<const float4*>(p)[lane];   // 128/32 = 4 elems/lane
    float s = v.x * v.x + v.y * v.y + v.z * v.z + v.w * v.w;
    #pragma unroll
    for (int o = 16; o > 0; o >>= 1) s += __shfl_xor_sync(0xFFFFFFFFu, s, o);
    if (lane == 0) {
        float r = rsqrtf(s);
        if (w < R_TOTAL) { g_xsq[w] = s; g_xrn[w] = r; }
        else             { g_ysq[w - R_TOTAL] = s; g_yrn[w - R_TOTAL] = r; }
    }
}

// ---------------- packed f32x2 helpers ----------------
__device__ __forceinline__ u64 ffma2(u64 a, u64 b, u64 c) {
    u64 d;
    asm("fma.rn.f32x2 %0, %1, %2, %3;" : "=l"(d) : "l"(a), "l"(b), "l"(c));
    return d;
}
__device__ __forceinline__ float f2lo(u64 d) { return __uint_as_float((unsigned)(d & 0xFFFFFFFFu)); }
__device__ __forceinline__ float f2hi(u64 d) { return __uint_as_float((unsigned)(d >> 32)); }

// ---------------- main distance kernel ----------------
__global__ void __launch_bounds__(512)
dist_kernel(const float* __restrict__ x, const float* __restrict__ y,
            float* __restrict__ out) {
    __shared__ __align__(16) float xs[BM][LDW];
    __shared__ __align__(16) float ys[BN][LDW];

    const int R0 = blockIdx.x * BM;       // grid.x = 16
    const int C0 = blockIdx.y * BN;       // grid.y = 8
    const int t  = threadIdx.x;
    const int tx = t & 15;                // 16 col-threads
    const int ty = t >> 4;                // 32 row-threads

    const u64 NEG1 = 0xBF800000BF800000ULL; // (-1.f,-1.f)

    float acc1[4][4];                     // L1 sums
    u64   acc2[4][4];                     // packed f32x2 sum of squares
    #pragma unroll
    for (int i = 0; i < 4; i++)
        #pragma unroll
        for (int j = 0; j < 4; j++) { acc1[i][j] = 0.0f; acc2[i][j] = 0ULL; }

    const int lr = t >> 3;                // 0..63
    const int q  = t & 7;                 // 0..7 (float4 slot within 32-col chunk)

    for (int d0 = 0; d0 < D_DIM; d0 += DK) {
        // ---- stage x chunk: 128 rows x 32 cols (2 float4 per thread) ----
        #pragma unroll
        for (int s = 0; s < 2; s++) {
            int row = lr + 64 * s;
            float4 v = *reinterpret_cast<const float4*>(
                x + (size_t)(R0 + row) * D_DIM + d0 + q * 4);
            *reinterpret_cast<float4*>(&xs[row][q * 4]) = v;
        }
        // ---- stage y chunk: 64 rows x 32 cols (1 float4 per thread) ----
        {
            float4 v = *reinterpret_cast<const float4*>(
                y + (size_t)(C0 + lr) * D_DIM + d0 + q * 4);
            *reinterpret_cast<float4*>(&ys[lr][q * 4]) = v;
        }
        __syncthreads();

        #pragma unroll 2
        for (int dd = 0; dd < DK; dd += 4) {
            ull2 xv[4], yv[4];
            #pragma unroll
            for (int i = 0; i < 4; i++)
                xv[i] = *reinterpret_cast<const ull2*>(&xs[ty + 32 * i][dd]);
            #pragma unroll
            for (int j = 0; j < 4; j++)
                yv[j] = *reinterpret_cast<const ull2*>(&ys[tx + 16 * j][dd]);

            #pragma unroll
            for (int i = 0; i < 4; i++) {
                #pragma unroll
                for (int j = 0; j < 4; j++) {
                    u64 dA = ffma2(yv[j].x, NEG1, xv[i].x);   // x - y (2 lanes)
                    u64 dB = ffma2(yv[j].y, NEG1, xv[i].y);
                    acc2[i][j] = ffma2(dA, dA, acc2[i][j]);
                    acc2[i][j] = ffma2(dB, dB, acc2[i][j]);
                    acc1[i][j] += fabsf(f2lo(dA));
                    acc1[i][j] += fabsf(f2hi(dA));
                    acc1[i][j] += fabsf(f2lo(dB));
                    acc1[i][j] += fabsf(f2hi(dB));
                }
            }
        }
        __syncthreads();
    }

    // ---- epilogue: cos / p1 / p2 ----
    #pragma unroll
    for (int i = 0; i < 4; i++) {
        int gr = R0 + ty + 32 * i;
        float xsq = g_xsq[gr];
        float xrn = g_xrn[gr];
        #pragma unroll
        for (int j = 0; j < 4; j++) {
            int gc = C0 + tx + 16 * j;
            float s2  = f2lo(acc2[i][j]) + f2hi(acc2[i][j]);
            float p2  = sqrtf(fmaxf(s2, 0.0f));
            float dot = 0.5f * (xsq + g_ysq[gc] - s2);
            float cosv = dot * xrn * g_yrn[gc];
            size_t idx = ((size_t)gr * C_TOTAL + gc) * 3;
            out[idx + 0] = cosv;
            out[idx + 1] = acc1[i][j];
            out[idx + 2] = p2;
        }
    }
}

extern "C" void kernel_launch(void* const* d_in, const int* in_sizes, int n_in,
                              void* d_out, int out_size) {
    const float* x = (const float*)d_in[0];   // [4,512,128]
    const float* y = (const float*)d_in[1];   // [512,128]
    float* out = (float*)d_out;               // [4,512,512,3]

    // 2560 rows, 1 warp each -> 2560*32 threads
    norms_kernel<<<(2560 * 32 + 255) / 256, 256>>>(x, y);

    dim3 grid(R_TOTAL / BM, C_TOTAL / BN);    // 16 x 8 = 128 blocks (1 wave)
    dist_kernel<<<grid, 512>>>(x, y, out);
}

// round 3
// speedup vs baseline: 1.0012x; 1.0012x over previous
#include <cuda_runtime.h>
#include <cstdint>

// x [4,512,128] f32, y [512,128] f32 -> out [4,512,512,3] f32 (cos, L1, L2)
#define R_TOTAL 2048
#define C_TOTAL 512
#define D_DIM   128

#define BM 128
#define BN 64
#define DK 32
#define PADW 4
#define LDW (DK + PADW)          // 36 words/row, 144B (16B-aligned stride)
#define BUFW ((BM + BN) * LDW)   // words per buffer
#define SMEM_BYTES (2 * BUFW * 4)

typedef unsigned long long u64;
struct __align__(16) ull2 { u64 x, y; };

// ---------------- precomputed norms ----------------
__device__ float g_xsq[R_TOTAL];
__device__ float g_xrn[R_TOTAL];
__device__ float g_ysq[C_TOTAL];
__device__ float g_yrn[C_TOTAL];

__global__ void norms_kernel(const float* __restrict__ x,
                             const float* __restrict__ y) {
    int w    = (blockIdx.x * blockDim.x + threadIdx.x) >> 5;
    int lane = threadIdx.x & 31;
    if (w >= R_TOTAL + C_TOTAL) return;
    const float* p = (w < R_TOTAL) ? (x + (size_t)w * D_DIM)
                                   : (y + (size_t)(w - R_TOTAL) * D_DIM);
    float4 v = reinterpret_cast<const float4*>(p)[lane];
    float s = v.x * v.x + v.y * v.y + v.z * v.z + v.w * v.w;
    #pragma unroll
    for (int o = 16; o > 0; o >>= 1) s += __shfl_xor_sync(0xFFFFFFFFu, s, o);
    if (lane == 0) {
        float r = rsqrtf(s);
        if (w < R_TOTAL) { g_xsq[w] = s; g_xrn[w] = r; }
        else             { g_ysq[w - R_TOTAL] = s; g_yrn[w - R_TOTAL] = r; }
    }
}

// ---------------- packed f32x2 helpers ----------------
__device__ __forceinline__ u64 ffma2(u64 a, u64 b, u64 c) {
    u64 d;
    asm("fma.rn.f32x2 %0, %1, %2, %3;" : "=l"(d) : "l"(a), "l"(b), "l"(c));
    return d;
}
__device__ __forceinline__ u64 fadd2(u64 a, u64 b) {
    u64 d;
    asm("add.rn.f32x2 %0, %1, %2;" : "=l"(d) : "l"(a), "l"(b));
    return d;
}
__device__ __forceinline__ float f2lo(u64 d) { return __uint_as_float((unsigned)(d & 0xFFFFFFFFu)); }
__device__ __forceinline__ float f2hi(u64 d) { return __uint_as_float((unsigned)(d >> 32)); }

// ---------------- main distance kernel ----------------
__global__ void __launch_bounds__(512)
dist_kernel(const float* __restrict__ x, const float* __restrict__ y,
            float* __restrict__ out) {
    extern __shared__ __align__(16) float sm[];

    const int R0 = blockIdx.x * BM;
    const int C0 = blockIdx.y * BN;
    const int t  = threadIdx.x;
    const int tx = t & 15;
    const int ty = t >> 4;

    const u64 NEG1 = 0xBF800000BF800000ULL;   // (-1.f, -1.f)
    const u64 ABSM = 0x7FFFFFFF7FFFFFFFULL;   // packed abs mask

    u64 acc1[4][4];   // packed L1 sums
    u64 acc2[4][4];   // packed sum of squares
    #pragma unroll
    for (int i = 0; i < 4; i++)
        #pragma unroll
        for (int j = 0; j < 4; j++) { acc1[i][j] = 0ULL; acc2[i][j] = 0ULL; }

    const int lr = t >> 3;   // 0..63
    const int q  = t & 7;    // float4 slot in 32-col chunk

    // smem accessors: buffer b, x rows then y rows
    float* xsb[2] = { sm,            sm + BUFW };
    float* ysb[2] = { sm + BM * LDW, sm + BUFW + BM * LDW };

    // ---- preload chunk 0 into buffer 0 ----
    {
        float4 a0 = *reinterpret_cast<const float4*>(x + (size_t)(R0 + lr) * D_DIM + q * 4);
        float4 a1 = *reinterpret_cast<const float4*>(x + (size_t)(R0 + lr + 64) * D_DIM + q * 4);
        float4 b0 = *reinterpret_cast<const float4*>(y + (size_t)(C0 + lr) * D_DIM + q * 4);
        *reinterpret_cast<float4*>(&xsb[0][lr * LDW + q * 4]) = a0;
        *reinterpret_cast<float4*>(&xsb[0][(lr + 64) * LDW + q * 4]) = a1;
        *reinterpret_cast<float4*>(&ysb[0][lr * LDW + q * 4]) = b0;
    }
    __syncthreads();

    int p = 0;
    #pragma unroll
    for (int k = 0; k < D_DIM / DK; k++) {
        float4 pa0, pa1, pb0;
        if (k + 1 < D_DIM / DK) {
            int d0 = (k + 1) * DK;
            pa0 = *reinterpret_cast<const float4*>(x + (size_t)(R0 + lr) * D_DIM + d0 + q * 4);
            pa1 = *reinterpret_cast<const float4*>(x + (size_t)(R0 + lr + 64) * D_DIM + d0 + q * 4);
            pb0 = *reinterpret_cast<const float4*>(y + (size_t)(C0 + lr) * D_DIM + d0 + q * 4);
        }

        const float* xs = xsb[p];
        const float* ys = ysb[p];

        #pragma unroll
        for (int dd = 0; dd < DK; dd += 4) {
            ull2 xv[4], yv[4];
            #pragma unroll
            for (int i = 0; i < 4; i++)
                xv[i] = *reinterpret_cast<const ull2*>(&xs[(ty + 32 * i) * LDW + dd]);
            #pragma unroll
            for (int j = 0; j < 4; j++)
                yv[j] = *reinterpret_cast<const ull2*>(&ys[(tx + 16 * j) * LDW + dd]);

            #pragma unroll
            for (int i = 0; i < 4; i++) {
                #pragma unroll
                for (int j = 0; j < 4; j++) {
                    u64 dA = ffma2(yv[j].x, NEG1, xv[i].x);   // x - y (2 lanes)
                    u64 dB = ffma2(yv[j].y, NEG1, xv[i].y);
                    acc2[i][j] = ffma2(dA, dA, acc2[i][j]);
                    acc2[i][j] = ffma2(dB, dB, acc2[i][j]);
                    acc1[i][j] = fadd2(acc1[i][j], dA & ABSM); // LOP3 (alu) + FADD2 (fma)
                    acc1[i][j] = fadd2(acc1[i][j], dB & ABSM);
                }
            }
        }

        if (k + 1 < D_DIM / DK) {
            float* xn = xsb[p ^ 1];
            float* yn = ysb[p ^ 1];
            *reinterpret_cast<float4*>(&xn[lr * LDW + q * 4]) = pa0;
            *reinterpret_cast<float4*>(&xn[(lr + 64) * LDW + q * 4]) = pa1;
            *reinterpret_cast<float4*>(&yn[lr * LDW + q * 4]) = pb0;
        }
        __syncthreads();
        p ^= 1;
    }

    // ---- epilogue: cos / p1 / p2 ----
    #pragma unroll
    for (int i = 0; i < 4; i++) {
        int gr = R0 + ty + 32 * i;
        float xsq = g_xsq[gr];
        float xrn = g_xrn[gr];
        #pragma unroll
        for (int j = 0; j < 4; j++) {
            int gc = C0 + tx + 16 * j;
            float s2 = f2lo(acc2[i][j]) + f2hi(acc2[i][j]);
            float s1 = f2lo(acc1[i][j]) + f2hi(acc1[i][j]);
            float p2 = sqrtf(fmaxf(s2, 0.0f));
            float dot = 0.5f * (xsq + g_ysq[gc] - s2);
            float cosv = dot * xrn * g_yrn[gc];
            size_t idx = ((size_t)gr * C_TOTAL + gc) * 3;
            out[idx + 0] = cosv;
            out[idx + 1] = s1;
            out[idx + 2] = p2;
        }
    }
}

extern "C" void kernel_launch(void* const* d_in, const int* in_sizes, int n_in,
                              void* d_out, int out_size) {
    const float* x = (const float*)d_in[0];
    const float* y = (const float*)d_in[1];
    float* out = (float*)d_out;

    cudaFuncSetAttribute(dist_kernel,
                         cudaFuncAttributeMaxDynamicSharedMemorySize, SMEM_BYTES);

    norms_kernel<<<(2560 * 32 + 255) / 256, 256>>>(x, y);

    dim3 grid(R_TOTAL / BM, C_TOTAL / BN);   // 16 x 8 = 128 blocks
    dist_kernel<<<grid, 512, SMEM_BYTES>>>(x, y, out);
}